// round 2
// baseline (speedup 1.0000x reference)
#include <cuda_runtime.h>
#include <math.h>

#define N_ROWS 8192
#define K_CODES 8192
#define DIM 256
#define KSPL 4
#define RSPL 4

// ---- scratch (static __device__ arrays: no allocation) ----
__device__ float g_zn[N_ROWS * DIM];      // normalized z rows
__device__ float g_en[K_CODES * DIM];     // normalized emb rows
__device__ float g_en2[K_CODES];          // sum of squares of normalized emb rows (~1)
__device__ float g_pKey[KSPL * N_ROWS];
__device__ int   g_pIdx[KSPL * N_ROWS];
__device__ float g_pZ[KSPL * N_ROWS];
__device__ int   g_idx[N_ROWS];
__device__ float g_invZ[N_ROWS];
__device__ float g_ap[K_CODES];
__device__ int   g_counts[K_CODES];
__device__ float g_commit[1];

// output layout (float32): [z_q_out 8*1024*256][idx 8192][loss][perplexity]
#define OFF_IDX  (N_ROWS * DIM)
#define OFF_LOSS (OFF_IDX + N_ROWS)
#define OFF_PERP (OFF_LOSS + 1)

// ---------------------------------------------------------------------------
__global__ void init_kernel() {
    int t = blockIdx.x * blockDim.x + threadIdx.x;
    if (t < K_CODES) { g_ap[t] = 0.f; g_counts[t] = 0; }
    if (t == 0) g_commit[0] = 0.f;
}

// ---------------------------------------------------------------------------
// one warp per row: L2-normalize z and emb
__global__ void norm_kernel(const float* __restrict__ z, const float* __restrict__ emb) {
    int w = (blockIdx.x * blockDim.x + threadIdx.x) >> 5;
    int lane = threadIdx.x & 31;
    if (w >= N_ROWS + K_CODES) return;
    const float* src;
    float* dst;
    if (w < N_ROWS) { src = z + (size_t)w * DIM; dst = g_zn + (size_t)w * DIM; }
    else            { int r = w - N_ROWS; src = emb + (size_t)r * DIM; dst = g_en + (size_t)r * DIM; }

    float4 v0 = reinterpret_cast<const float4*>(src)[lane * 2];
    float4 v1 = reinterpret_cast<const float4*>(src)[lane * 2 + 1];
    float ss = v0.x*v0.x + v0.y*v0.y + v0.z*v0.z + v0.w*v0.w
             + v1.x*v1.x + v1.y*v1.y + v1.z*v1.z + v1.w*v1.w;
#pragma unroll
    for (int o = 16; o; o >>= 1) ss += __shfl_xor_sync(0xffffffffu, ss, o);
    float sc = 1.f / fmaxf(sqrtf(ss), 1e-12f);
    v0.x *= sc; v0.y *= sc; v0.z *= sc; v0.w *= sc;
    v1.x *= sc; v1.y *= sc; v1.z *= sc; v1.w *= sc;
    reinterpret_cast<float4*>(dst)[lane * 2]     = v0;
    reinterpret_cast<float4*>(dst)[lane * 2 + 1] = v1;
    if (w >= N_ROWS && lane == 0) g_en2[w - N_ROWS] = ss * sc * sc;
}

// ---------------------------------------------------------------------------
// tiled fp32 GEMM constants
#define BM 128
#define BN 128
#define BD 32
#define TM 8
#define TN 8
#define SPAD 4

// pass A: per-row argmin(d) key + Z = sum exp(-20 s), partial per K-split
__global__ void __launch_bounds__(256, 2) passA_kernel() {
    __shared__ float As[BD][BM + SPAD];
    __shared__ float Bs[BD][BN + SPAD];
    __shared__ float sE2[BN];
    const int t  = threadIdx.x;
    const int tx = t & 15, ty = t >> 4;
    const int row0 = blockIdx.x * BM;
    const int ks = blockIdx.y;
    const int KCH = K_CODES / KSPL;   // 2048

    float bestKey[TM], zAcc[TM];
    int bestIdx[TM];
#pragma unroll
    for (int i = 0; i < TM; i++) { bestKey[i] = -3.4e38f; bestIdx[i] = 0; zAcc[i] = 0.f; }

    for (int kt = 0; kt < KCH / BN; kt++) {
        const int col0 = ks * KCH + kt * BN;
        __syncthreads();                       // protect sE2 / smem reuse
        if (t < BN) sE2[t] = g_en2[col0 + t];

        float acc[TM][TN];
#pragma unroll
        for (int i = 0; i < TM; i++)
#pragma unroll
            for (int j = 0; j < TN; j++) acc[i][j] = 0.f;

        for (int d0 = 0; d0 < DIM; d0 += BD) {
            __syncthreads();
#pragma unroll
            for (int it = 0; it < 4; it++) {
                int e = it * 256 + t;          // 0..1023 float4s, 8 per row
                int m = e >> 3;
                int dv = e & 7;
                float4 va = reinterpret_cast<const float4*>(g_zn)[(size_t)(row0 + m) * (DIM/4) + (d0 >> 2) + dv];
                As[dv*4+0][m] = va.x; As[dv*4+1][m] = va.y; As[dv*4+2][m] = va.z; As[dv*4+3][m] = va.w;
                float4 vb = reinterpret_cast<const float4*>(g_en)[(size_t)(col0 + m) * (DIM/4) + (d0 >> 2) + dv];
                Bs[dv*4+0][m] = vb.x; Bs[dv*4+1][m] = vb.y; Bs[dv*4+2][m] = vb.z; Bs[dv*4+3][m] = vb.w;
            }
            __syncthreads();
#pragma unroll
            for (int d = 0; d < BD; d++) {
                float4 a0 = *reinterpret_cast<const float4*>(&As[d][ty * TM]);
                float4 a1 = *reinterpret_cast<const float4*>(&As[d][ty * TM + 4]);
                float4 b0 = *reinterpret_cast<const float4*>(&Bs[d][tx * TN]);
                float4 b1 = *reinterpret_cast<const float4*>(&Bs[d][tx * TN + 4]);
                float a[TM] = {a0.x,a0.y,a0.z,a0.w,a1.x,a1.y,a1.z,a1.w};
                float b[TN] = {b0.x,b0.y,b0.z,b0.w,b1.x,b1.y,b1.z,b1.w};
#pragma unroll
                for (int i = 0; i < TM; i++)
#pragma unroll
                    for (int j = 0; j < TN; j++) acc[i][j] = fmaf(a[i], b[j], acc[i][j]);
            }
        }
        // per-row stats for this tile
#pragma unroll
        for (int i = 0; i < TM; i++) {
            float key = -3.4e38f; int kidx = 0; float zs = 0.f;
#pragma unroll
            for (int j = 0; j < TN; j++) {
                float s  = acc[i][j];
                float kj = fmaf(2.f, s, -sE2[tx * TN + j]);   // argmax(2s - en2) == argmin d
                if (kj > key) { key = kj; kidx = col0 + tx * TN + j; }
                zs += __expf(-20.f * s);
            }
#pragma unroll
            for (int off = 8; off > 0; off >>= 1) {            // reduce across 16-lane row group
                float ok = __shfl_xor_sync(0xffffffffu, key, off);
                int   oi = __shfl_xor_sync(0xffffffffu, kidx, off);
                float oz = __shfl_xor_sync(0xffffffffu, zs, off);
                if (ok > key || (ok == key && oi < kidx)) { key = ok; kidx = oi; }
                zs += oz;
            }
            if (key > bestKey[i] || (key == bestKey[i] && kidx < bestIdx[i])) { bestKey[i] = key; bestIdx[i] = kidx; }
            zAcc[i] += zs;
        }
    }
    if (tx == 0) {
#pragma unroll
        for (int i = 0; i < TM; i++) {
            int r = row0 + ty * TM + i;
            g_pKey[ks * N_ROWS + r] = bestKey[i];
            g_pIdx[ks * N_ROWS + r] = bestIdx[i];
            g_pZ[ks * N_ROWS + r]   = zAcc[i];
        }
    }
}

// combine K-split partials -> final idx and 1/Z per row
__global__ void combine_kernel() {
    int n = blockIdx.x * blockDim.x + threadIdx.x;
    if (n >= N_ROWS) return;
    float best = -3.4e38f, Z = 0.f;
    int bi = 0;
#pragma unroll
    for (int ks = 0; ks < KSPL; ks++) {
        float k = g_pKey[ks * N_ROWS + n];
        int   i = g_pIdx[ks * N_ROWS + n];
        if (k > best || (k == best && i < bi)) { best = k; bi = i; }
        Z += g_pZ[ks * N_ROWS + n];
    }
    g_idx[n]  = bi;
    g_invZ[n] = 1.f / Z;
}

// pass B: recompute S tiles, accumulate ap[k] = sum_n exp(-20 s) / Z_n
__global__ void __launch_bounds__(256, 2) passB_kernel() {
    __shared__ float As[BD][BM + SPAD];
    __shared__ float Bs[BD][BN + SPAD];
    __shared__ float sInv[BM];
    __shared__ float red[16][BN];
    const int t  = threadIdx.x;
    const int tx = t & 15, ty = t >> 4;
    const int col0 = blockIdx.x * BN;
    const int rs = blockIdx.y;
    const int RCH = N_ROWS / RSPL;     // 2048

    float colAcc[TN];
#pragma unroll
    for (int j = 0; j < TN; j++) colAcc[j] = 0.f;

    for (int rt = 0; rt < RCH / BM; rt++) {
        const int row0 = rs * RCH + rt * BM;
        __syncthreads();
        if (t < BM) sInv[t] = g_invZ[row0 + t];

        float acc[TM][TN];
#pragma unroll
        for (int i = 0; i < TM; i++)
#pragma unroll
            for (int j = 0; j < TN; j++) acc[i][j] = 0.f;

        for (int d0 = 0; d0 < DIM; d0 += BD) {
            __syncthreads();
#pragma unroll
            for (int it = 0; it < 4; it++) {
                int e = it * 256 + t;
                int m = e >> 3;
                int dv = e & 7;
                float4 va = reinterpret_cast<const float4*>(g_zn)[(size_t)(row0 + m) * (DIM/4) + (d0 >> 2) + dv];
                As[dv*4+0][m] = va.x; As[dv*4+1][m] = va.y; As[dv*4+2][m] = va.z; As[dv*4+3][m] = va.w;
                float4 vb = reinterpret_cast<const float4*>(g_en)[(size_t)(col0 + m) * (DIM/4) + (d0 >> 2) + dv];
                Bs[dv*4+0][m] = vb.x; Bs[dv*4+1][m] = vb.y; Bs[dv*4+2][m] = vb.z; Bs[dv*4+3][m] = vb.w;
            }
            __syncthreads();
#pragma unroll
            for (int d = 0; d < BD; d++) {
                float4 a0 = *reinterpret_cast<const float4*>(&As[d][ty * TM]);
                float4 a1 = *reinterpret_cast<const float4*>(&As[d][ty * TM + 4]);
                float4 b0 = *reinterpret_cast<const float4*>(&Bs[d][tx * TN]);
                float4 b1 = *reinterpret_cast<const float4*>(&Bs[d][tx * TN + 4]);
                float a[TM] = {a0.x,a0.y,a0.z,a0.w,a1.x,a1.y,a1.z,a1.w};
                float b[TN] = {b0.x,b0.y,b0.z,b0.w,b1.x,b1.y,b1.z,b1.w};
#pragma unroll
                for (int i = 0; i < TM; i++)
#pragma unroll
                    for (int j = 0; j < TN; j++) acc[i][j] = fmaf(a[i], b[j], acc[i][j]);
            }
        }
#pragma unroll
        for (int i = 0; i < TM; i++) {
            float w = sInv[ty * TM + i];
#pragma unroll
            for (int j = 0; j < TN; j++)
                colAcc[j] += __expf(-20.f * acc[i][j]) * w;
        }
    }
    __syncthreads();
#pragma unroll
    for (int j = 0; j < TN; j++) red[ty][tx * TN + j] = colAcc[j];
    __syncthreads();
    if (t < BN) {
        float s = 0.f;
#pragma unroll
        for (int y = 0; y < 16; y++) s += red[y][t];
        atomicAdd(&g_ap[col0 + t], s);
    }
}

// ---------------------------------------------------------------------------
// one warp per row: write z_q_out = en[idx], commit sumsq, histogram, idx out
__global__ void zq_kernel(float* __restrict__ out) {
    int n = (blockIdx.x * blockDim.x + threadIdx.x) >> 5;
    int lane = threadIdx.x & 31;
    if (n >= N_ROWS) return;
    int idx = g_idx[n];
    const float4* e  = reinterpret_cast<const float4*>(g_en + (size_t)idx * DIM);
    const float4* zr = reinterpret_cast<const float4*>(g_zn + (size_t)n * DIM);
    float4* o = reinterpret_cast<float4*>(out + (size_t)n * DIM);
    float4 e0 = e[lane * 2], e1 = e[lane * 2 + 1];
    float4 z0 = zr[lane * 2], z1 = zr[lane * 2 + 1];
    o[lane * 2]     = e0;
    o[lane * 2 + 1] = e1;
    float dx, ss = 0.f;
    dx = e0.x - z0.x; ss += dx * dx;  dx = e0.y - z0.y; ss += dx * dx;
    dx = e0.z - z0.z; ss += dx * dx;  dx = e0.w - z0.w; ss += dx * dx;
    dx = e1.x - z1.x; ss += dx * dx;  dx = e1.y - z1.y; ss += dx * dx;
    dx = e1.z - z1.z; ss += dx * dx;  dx = e1.w - z1.w; ss += dx * dx;
#pragma unroll
    for (int o2 = 16; o2; o2 >>= 1) ss += __shfl_xor_sync(0xffffffffu, ss, o2);
    if (lane == 0) {
        atomicAdd(&g_commit[0], ss);
        atomicAdd(&g_counts[idx], 1);
        out[OFF_IDX + n] = (float)idx;
    }
}

// final scalars: diversity loss, commit loss, perplexity
__global__ void finalize_kernel(float* __restrict__ out) {
    __shared__ float sdiv[256], sperp[256];
    int t = threadIdx.x;
    float dv = 0.f, pp = 0.f;
    for (int k = t; k < K_CODES; k += 256) {
        float apk = g_ap[k] * (1.0f / (float)N_ROWS);
        dv += apk * logf(apk);                                  // diversity = sum ap log ap
        float pr = (float)g_counts[k] * (1.0f / (float)N_ROWS);
        pp += pr * logf(pr + 1e-10f);
    }
    sdiv[t] = dv; sperp[t] = pp;
    __syncthreads();
    for (int s = 128; s; s >>= 1) {
        if (t < s) { sdiv[t] += sdiv[t + s]; sperp[t] += sperp[t + s]; }
        __syncthreads();
    }
    if (t == 0) {
        float commit = 1.25f * g_commit[0] / (float)(N_ROWS * DIM);
        out[OFF_LOSS] = commit + sdiv[0];
        out[OFF_PERP] = expf(-sperp[0]);
    }
}

// ---------------------------------------------------------------------------
extern "C" void kernel_launch(void* const* d_in, const int* in_sizes, int n_in,
                              void* d_out, int out_size) {
    const float* z   = (const float*)d_in[0];
    const float* emb = (const float*)d_in[1];
    float* out = (float*)d_out;

    init_kernel<<<(K_CODES + 255) / 256, 256>>>();
    norm_kernel<<<(N_ROWS + K_CODES) / 8, 256>>>(z, emb);
    passA_kernel<<<dim3(N_ROWS / BM, KSPL), 256>>>();
    combine_kernel<<<N_ROWS / 256, 256>>>();
    passB_kernel<<<dim3(K_CODES / BN, RSPL), 256>>>();
    zq_kernel<<<N_ROWS / 8, 256>>>(out);
    finalize_kernel<<<1, 256>>>(out);
}

// round 4
// speedup vs baseline: 1.1322x; 1.1322x over previous
#include <cuda_runtime.h>
#include <cuda_bf16.h>
#include <math.h>
#include <stdint.h>

#define N_ROWS 8192
#define K_CODES 8192
#define DIM 256
#define NSPLIT 64                 // col-tiles of 128
#define TAU 1e-5f

// ---------------- scratch (__device__ statics: no allocation) ----------------
__device__ float g_zn[N_ROWS * DIM];
__device__ float g_en[K_CODES * DIM];
__device__ float g_en2[K_CODES];
__device__ __nv_bfloat16 g_zh[N_ROWS * DIM];
__device__ __nv_bfloat16 g_zm[N_ROWS * DIM];
__device__ __nv_bfloat16 g_eh[K_CODES * DIM];
__device__ __nv_bfloat16 g_em[K_CODES * DIM];
__device__ __nv_bfloat16 g_E[(size_t)N_ROWS * K_CODES];   // E[n][k] = exp(-20 s), 128 MB
__device__ float g_pT1[NSPLIT * N_ROWS];
__device__ float g_pT2[NSPLIT * N_ROWS];
__device__ float g_pZ [NSPLIT * N_ROWS];
__device__ int   g_pI1[NSPLIT * N_ROWS];
__device__ int   g_idx[N_ROWS];
__device__ float g_invZ[N_ROWS];
__device__ float g_ap[K_CODES];
__device__ int   g_counts[K_CODES];
__device__ float g_commit[1];
__device__ int   g_fixCnt[1];
__device__ int   g_fixList[N_ROWS];

#define OFF_IDX  (N_ROWS * DIM)
#define OFF_LOSS (OFF_IDX + N_ROWS)
#define OFF_PERP (OFF_LOSS + 1)

// ---------------- helpers ----------------
__device__ __forceinline__ uint32_t smem_u32(const void* p) {
    uint32_t a;
    asm("{ .reg .u64 t; cvta.to.shared.u64 t, %1; cvt.u32.u64 %0, t; }" : "=r"(a) : "l"(p));
    return a;
}
__device__ __forceinline__ void cp_async16(uint32_t dst, const void* src) {
    asm volatile("cp.async.cg.shared.global [%0], [%1], 16;" :: "r"(dst), "l"(src));
}
__device__ __forceinline__ void cp_commit() { asm volatile("cp.async.commit_group;"); }
__device__ __forceinline__ void cp_wait1()  { asm volatile("cp.async.wait_group 1;"); }
__device__ __forceinline__ void cp_wait0()  { asm volatile("cp.async.wait_group 0;"); }

__device__ __forceinline__ uint32_t lds32(uint32_t addr) {
    uint32_t v;
    asm volatile("ld.shared.b32 %0, [%1];" : "=r"(v) : "r"(addr));
    return v;
}
__device__ __forceinline__ void mma_bf16(float* d, const uint32_t* a, const uint32_t* b) {
    asm volatile(
        "mma.sync.aligned.m16n8k16.row.col.f32.bf16.bf16.f32 "
        "{%0,%1,%2,%3}, {%4,%5,%6,%7}, {%8,%9}, {%0,%1,%2,%3};"
        : "+f"(d[0]), "+f"(d[1]), "+f"(d[2]), "+f"(d[3])
        : "r"(a[0]), "r"(a[1]), "r"(a[2]), "r"(a[3]), "r"(b[0]), "r"(b[1]));
}

// swizzled byte offset within one 128-row x 64-k bf16 plane (128B rows)
__device__ __forceinline__ uint32_t sw_off(int r, int k) {
    return (uint32_t)(r * 128 + ((((k >> 3) ^ (r & 7)) & 7) << 4) + (k & 7) * 2);
}

// smem layout (dynamic): 2 stages x (A 32KB + B 32KB) = 128KB, then en2 (512B), comb (4KB)
#define STAGE_BYTES 65536
#define B_IN_STAGE  32768
#define PLANE       16384
#define EN2_OFF     131072
#define COMB_OFF    131584
#define SMEM_TOTAL  (131584 + 4096)

// ---------------------------------------------------------------------------
__global__ void init_kernel() {
    int t = blockIdx.x * blockDim.x + threadIdx.x;
    if (t < K_CODES) g_counts[t] = 0;
    if (t == 0) { g_commit[0] = 0.f; g_fixCnt[0] = 0; }
}

// ---------------------------------------------------------------------------
// one warp per row: L2-normalize + bf16 hi/mid split
__global__ void norm_split_kernel(const float* __restrict__ z, const float* __restrict__ emb) {
    int w = (blockIdx.x * blockDim.x + threadIdx.x) >> 5;
    int lane = threadIdx.x & 31;
    if (w >= N_ROWS + K_CODES) return;
    const float* src; float* dst; __nv_bfloat16 *dh, *dm; int row;
    if (w < N_ROWS) { row = w; src = z + (size_t)row * DIM; dst = g_zn + (size_t)row * DIM; dh = g_zh; dm = g_zm; }
    else { row = w - N_ROWS; src = emb + (size_t)row * DIM; dst = g_en + (size_t)row * DIM; dh = g_eh; dm = g_em; }

    float4 v0 = reinterpret_cast<const float4*>(src)[lane * 2];
    float4 v1 = reinterpret_cast<const float4*>(src)[lane * 2 + 1];
    float ss = v0.x*v0.x + v0.y*v0.y + v0.z*v0.z + v0.w*v0.w
             + v1.x*v1.x + v1.y*v1.y + v1.z*v1.z + v1.w*v1.w;
#pragma unroll
    for (int o = 16; o; o >>= 1) ss += __shfl_xor_sync(0xffffffffu, ss, o);
    float sc = 1.f / fmaxf(sqrtf(ss), 1e-12f);
    v0.x *= sc; v0.y *= sc; v0.z *= sc; v0.w *= sc;
    v1.x *= sc; v1.y *= sc; v1.z *= sc; v1.w *= sc;
    reinterpret_cast<float4*>(dst)[lane * 2]     = v0;
    reinterpret_cast<float4*>(dst)[lane * 2 + 1] = v1;

    float vv[8] = {v0.x, v0.y, v0.z, v0.w, v1.x, v1.y, v1.z, v1.w};
    alignas(16) __nv_bfloat16 hh[8];
    alignas(16) __nv_bfloat16 mm[8];
#pragma unroll
    for (int i = 0; i < 8; i++) {
        __nv_bfloat16 h = __float2bfloat16(vv[i]);
        hh[i] = h;
        mm[i] = __float2bfloat16(vv[i] - __bfloat162float(h));
    }
    *reinterpret_cast<uint4*>(dh + (size_t)row * DIM + lane * 8) = *reinterpret_cast<uint4*>(hh);
    *reinterpret_cast<uint4*>(dm + (size_t)row * DIM + lane * 8) = *reinterpret_cast<uint4*>(mm);
    if (w >= N_ROWS && lane == 0) g_en2[row] = ss * sc * sc;
}

// ---------------------------------------------------------------------------
// issue one K-chunk (64) of A (z rows) + B (e rows) into stage buffer
__device__ __forceinline__ void issue_stage(uint32_t sb, int stage, int kc, int row0, int col0, int t) {
    uint32_t base = sb + stage * STAGE_BYTES;
#pragma unroll
    for (int i = 0; i < 8; i++) {          // A: 2048 vec16 = 2sp x 128r x 8g
        int v = i * 256 + t;
        int sp = v >> 10, r = (v >> 3) & 127, g = v & 7;
        const __nv_bfloat16* src = (sp ? g_zm : g_zh) + (size_t)(row0 + r) * DIM + kc * 64 + g * 8;
        cp_async16(base + sp * PLANE + (uint32_t)(r * 128 + (((g ^ (r & 7)) & 7) << 4)), src);
    }
#pragma unroll
    for (int i = 0; i < 8; i++) {          // B
        int v = i * 256 + t;
        int sp = v >> 10, r = (v >> 3) & 127, g = v & 7;
        const __nv_bfloat16* src = (sp ? g_em : g_eh) + (size_t)(col0 + r) * DIM + kc * 64 + g * 8;
        cp_async16(base + B_IN_STAGE + sp * PLANE + (uint32_t)(r * 128 + (((g ^ (r & 7)) & 7) << 4)), src);
    }
    cp_commit();
}

// ---------------------------------------------------------------------------
// mma.sync GEMM: S(128x128) = Zn * En^T via 3-product bf16 split.
// Epilogue: per-row top1/top2 key, Z, E store.
__global__ void __launch_bounds__(256, 1) gemm_kernel() {
    extern __shared__ char smem[];
    const uint32_t sb = smem_u32(smem);
    const int t = threadIdx.x, w = t >> 5, lane = t & 31;
    const int wm = w & 3, wn = w >> 2;            // warp grid 4(m) x 2(n)
    const int lrow = lane >> 2, kq = (lane & 3) * 2;
    const int row0 = blockIdx.x * 128;
    const int col0 = blockIdx.y * 128;

    float acc[2][8][4];
#pragma unroll
    for (int m = 0; m < 2; m++)
#pragma unroll
        for (int n = 0; n < 8; n++)
#pragma unroll
            for (int c = 0; c < 4; c++) acc[m][n][c] = 0.f;

    if (t < 128) *(float*)(smem + EN2_OFF + t * 4) = g_en2[col0 + t];

    issue_stage(sb, 0, 0, row0, col0, t);

    for (int kc = 0; kc < 4; kc++) {
        if (kc < 3) issue_stage(sb, (kc + 1) & 1, kc + 1, row0, col0, t);
        if (kc < 3) cp_wait1(); else cp_wait0();
        __syncthreads();

        uint32_t Ab = sb + (kc & 1) * STAGE_BYTES;
        uint32_t Bb = Ab + B_IN_STAGE;
#pragma unroll
        for (int ks = 0; ks < 4; ks++) {
            int kb = ks * 16 + kq;
            uint32_t aH[2][4], aM[2][4], bH[8][2], bM[8][2];
#pragma unroll
            for (int m = 0; m < 2; m++) {
                int r = wm * 32 + m * 16 + lrow;
                aH[m][0] = lds32(Ab + sw_off(r, kb));
                aH[m][1] = lds32(Ab + sw_off(r + 8, kb));
                aH[m][2] = lds32(Ab + sw_off(r, kb + 8));
                aH[m][3] = lds32(Ab + sw_off(r + 8, kb + 8));
                aM[m][0] = lds32(Ab + PLANE + sw_off(r, kb));
                aM[m][1] = lds32(Ab + PLANE + sw_off(r + 8, kb));
                aM[m][2] = lds32(Ab + PLANE + sw_off(r, kb + 8));
                aM[m][3] = lds32(Ab + PLANE + sw_off(r + 8, kb + 8));
            }
#pragma unroll
            for (int n = 0; n < 8; n++) {
                int rb = wn * 64 + n * 8 + lrow;
                bH[n][0] = lds32(Bb + sw_off(rb, kb));
                bH[n][1] = lds32(Bb + sw_off(rb, kb + 8));
                bM[n][0] = lds32(Bb + PLANE + sw_off(rb, kb));
                bM[n][1] = lds32(Bb + PLANE + sw_off(rb, kb + 8));
            }
#pragma unroll
            for (int m = 0; m < 2; m++)
#pragma unroll
                for (int n = 0; n < 8; n++) {
                    mma_bf16(acc[m][n], aH[m], bH[n]);   // zh * eh
                    mma_bf16(acc[m][n], aH[m], bM[n]);   // zh * em
                    mma_bf16(acc[m][n], aM[m], bH[n]);   // zm * eh
                }
        }
        __syncthreads();
    }

    // ---- epilogue ----
    const float* sE2 = (const float*)(smem + EN2_OFF);
    float* sT1 = (float*)(smem + COMB_OFF);
    float* sT2 = sT1 + 256;
    float* sZ  = sT2 + 256;
    int*   sI1 = (int*)(sZ + 256);

#pragma unroll
    for (int m = 0; m < 2; m++)
#pragma unroll
        for (int rh = 0; rh < 2; rh++) {
            int rloc = wm * 32 + m * 16 + rh * 8 + lrow;
            int rowg = row0 + rloc;
            float t1 = -3.4e38f, t2 = -3.4e38f, z = 0.f;
            int i1 = 0x7fffffff;
            uint32_t* erow = reinterpret_cast<uint32_t*>(g_E + (size_t)rowg * K_CODES);
#pragma unroll
            for (int n = 0; n < 8; n++) {
                int cl = wn * 64 + n * 8 + kq;        // local col
                float s0 = acc[m][n][rh * 2 + 0];
                float s1 = acc[m][n][rh * 2 + 1];
                float k0 = fmaf(2.f, s0, -sE2[cl]);
                float k1 = fmaf(2.f, s1, -sE2[cl + 1]);
                float e0 = __expf(-20.f * s0);
                float e1 = __expf(-20.f * s1);
                z += e0 + e1;
                __nv_bfloat162 p = __floats2bfloat162_rn(e0, e1);
                erow[(col0 + cl) >> 1] = *reinterpret_cast<uint32_t*>(&p);
                int g0 = col0 + cl, g1 = g0 + 1;
                if (k0 > t1 || (k0 == t1 && g0 < i1)) { t2 = t1; t1 = k0; i1 = g0; } else t2 = fmaxf(t2, k0);
                if (k1 > t1 || (k1 == t1 && g1 < i1)) { t2 = t1; t1 = k1; i1 = g1; } else t2 = fmaxf(t2, k1);
            }
            // reduce across the 4 lanes of the quad (same row, different cols)
#pragma unroll
            for (int off = 1; off <= 2; off <<= 1) {
                float ok = __shfl_xor_sync(0xffffffffu, t1, off);
                int   oi = __shfl_xor_sync(0xffffffffu, i1, off);
                float o2 = __shfl_xor_sync(0xffffffffu, t2, off);
                float oz = __shfl_xor_sync(0xffffffffu, z, off);
                if (ok > t1 || (ok == t1 && oi < i1)) { t2 = fmaxf(t1, o2); t1 = ok; i1 = oi; }
                else t2 = fmaxf(t2, ok);
                z += oz;
            }
            if ((lane & 3) == 0) {
                int slot = rloc * 2 + wn;
                sT1[slot] = t1; sT2[slot] = t2; sZ[slot] = z; sI1[slot] = i1;
            }
        }
    __syncthreads();
    if (t < 128) {
        float a1 = sT1[t * 2], a2 = sT2[t * 2];       int ai = sI1[t * 2];
        float b1 = sT1[t * 2 + 1], b2 = sT2[t * 2 + 1]; int bi = sI1[t * 2 + 1];
        float T1, T2; int I1;
        if (b1 > a1 || (b1 == a1 && bi < ai)) { T1 = b1; I1 = bi; T2 = fmaxf(a1, b2); }
        else                                  { T1 = a1; I1 = ai; T2 = fmaxf(b1, a2); }
        int g = blockIdx.y * N_ROWS + row0 + t;
        g_pT1[g] = T1; g_pT2[g] = T2; g_pI1[g] = I1; g_pZ[g] = sZ[t * 2] + sZ[t * 2 + 1];
    }
}

// ---------------------------------------------------------------------------
__global__ void combine_kernel() {
    int r = blockIdx.x * blockDim.x + threadIdx.x;
    if (r >= N_ROWS) return;
    float T1 = -3.4e38f, T2 = -3.4e38f, Z = 0.f;
    int I1 = 0x7fffffff;
    for (int s = 0; s < NSPLIT; s++) {
        float a1 = g_pT1[s * N_ROWS + r], a2 = g_pT2[s * N_ROWS + r];
        int ai = g_pI1[s * N_ROWS + r];
        if (a1 > T1 || (a1 == T1 && ai < I1)) { T2 = fmaxf(T1, a2); T1 = a1; I1 = ai; }
        else T2 = fmaxf(T2, a1);
        Z += g_pZ[s * N_ROWS + r];
    }
    g_idx[r] = I1;
    g_invZ[r] = 1.f / Z;
    if (T1 - T2 < TAU) {
        int p = atomicAdd(&g_fixCnt[0], 1);
        g_fixList[p] = r;
    }
}

// exact fp32 argmin rescore for ambiguous rows
__global__ void fixup_kernel() {
    __shared__ float sz[DIM];
    __shared__ float sKey[256];
    __shared__ int   sIdx[256];
    int t = threadIdx.x;
    int cnt = g_fixCnt[0];
    for (int i = blockIdx.x; i < cnt; i += gridDim.x) {
        int r = g_fixList[i];
        __syncthreads();
        for (int f = t; f < DIM; f += 256) sz[f] = g_zn[(size_t)r * DIM + f];
        __syncthreads();
        float bk = -3.4e38f; int bi = 0x7fffffff;
        for (int k = t; k < K_CODES; k += 256) {
            const float* e = g_en + (size_t)k * DIM;
            float s = 0.f;
#pragma unroll 8
            for (int f = 0; f < DIM; f++) s = fmaf(sz[f], e[f], s);
            float key = fmaf(2.f, s, -g_en2[k]);
            if (key > bk || (key == bk && k < bi)) { bk = key; bi = k; }
        }
        sKey[t] = bk; sIdx[t] = bi;
        __syncthreads();
        for (int st = 128; st; st >>= 1) {
            if (t < st) {
                if (sKey[t + st] > sKey[t] ||
                    (sKey[t + st] == sKey[t] && sIdx[t + st] < sIdx[t])) {
                    sKey[t] = sKey[t + st]; sIdx[t] = sIdx[t + st];
                }
            }
            __syncthreads();
        }
        if (t == 0) g_idx[r] = sIdx[0];
        __syncthreads();
    }
}

// ---------------------------------------------------------------------------
// ap[k] = sum_n E[n][k] * invZ[n]; block b owns cols [b*128, b*128+128)
__global__ void passB_kernel() {
    __shared__ float sP[8][128];
    int t = threadIdx.x;
    int cg = t & 31;                 // 32 col-groups of 4
    int nh = t >> 5;                 // 8 n-streams
    int colb = blockIdx.x * 128 + cg * 4;
    float a0 = 0.f, a1 = 0.f, a2 = 0.f, a3 = 0.f;
    for (int n = nh; n < N_ROWS; n += 8) {
        float iz = g_invZ[n];
        uint2 v = *reinterpret_cast<const uint2*>(g_E + (size_t)n * K_CODES + colb);
        __nv_bfloat162 p0 = *reinterpret_cast<__nv_bfloat162*>(&v.x);
        __nv_bfloat162 p1 = *reinterpret_cast<__nv_bfloat162*>(&v.y);
        a0 += __bfloat162float(p0.x) * iz;
        a1 += __bfloat162float(p0.y) * iz;
        a2 += __bfloat162float(p1.x) * iz;
        a3 += __bfloat162float(p1.y) * iz;
    }
    sP[nh][cg * 4 + 0] = a0; sP[nh][cg * 4 + 1] = a1;
    sP[nh][cg * 4 + 2] = a2; sP[nh][cg * 4 + 3] = a3;
    __syncthreads();
    if (t < 128) {
        float s = 0.f;
#pragma unroll
        for (int y = 0; y < 8; y++) s += sP[y][t];
        g_ap[blockIdx.x * 128 + t] = s;
    }
}

// ---------------------------------------------------------------------------
__global__ void zq_kernel(float* __restrict__ out) {
    int n = (blockIdx.x * blockDim.x + threadIdx.x) >> 5;
    int lane = threadIdx.x & 31;
    if (n >= N_ROWS) return;
    int idx = g_idx[n];
    const float4* e  = reinterpret_cast<const float4*>(g_en + (size_t)idx * DIM);
    const float4* zr = reinterpret_cast<const float4*>(g_zn + (size_t)n * DIM);
    float4* o = reinterpret_cast<float4*>(out + (size_t)n * DIM);
    float4 e0 = e[lane * 2], e1 = e[lane * 2 + 1];
    float4 z0 = zr[lane * 2], z1 = zr[lane * 2 + 1];
    o[lane * 2] = e0; o[lane * 2 + 1] = e1;
    float dx, ss = 0.f;
    dx = e0.x - z0.x; ss += dx * dx;  dx = e0.y - z0.y; ss += dx * dx;
    dx = e0.z - z0.z; ss += dx * dx;  dx = e0.w - z0.w; ss += dx * dx;
    dx = e1.x - z1.x; ss += dx * dx;  dx = e1.y - z1.y; ss += dx * dx;
    dx = e1.z - z1.z; ss += dx * dx;  dx = e1.w - z1.w; ss += dx * dx;
#pragma unroll
    for (int o2 = 16; o2; o2 >>= 1) ss += __shfl_xor_sync(0xffffffffu, ss, o2);
    if (lane == 0) {
        atomicAdd(&g_commit[0], ss);
        atomicAdd(&g_counts[idx], 1);
        out[OFF_IDX + n] = (float)idx;
    }
}

__global__ void finalize_kernel(float* __restrict__ out) {
    __shared__ float sdiv[256], sperp[256];
    int t = threadIdx.x;
    float dv = 0.f, pp = 0.f;
    for (int k = t; k < K_CODES; k += 256) {
        float apk = g_ap[k] * (1.0f / (float)N_ROWS);
        dv += apk * logf(apk);
        float pr = (float)g_counts[k] * (1.0f / (float)N_ROWS);
        pp += pr * logf(pr + 1e-10f);
    }
    sdiv[t] = dv; sperp[t] = pp;
    __syncthreads();
    for (int s = 128; s; s >>= 1) {
        if (t < s) { sdiv[t] += sdiv[t + s]; sperp[t] += sperp[t + s]; }
        __syncthreads();
    }
    if (t == 0) {
        float commit = 1.25f * g_commit[0] / (float)(N_ROWS * DIM);
        out[OFF_LOSS] = commit + sdiv[0];
        out[OFF_PERP] = expf(-sperp[0]);
    }
}

// ---------------------------------------------------------------------------
extern "C" void kernel_launch(void* const* d_in, const int* in_sizes, int n_in,
                              void* d_out, int out_size) {
    const float* z   = (const float*)d_in[0];
    const float* emb = (const float*)d_in[1];
    float* out = (float*)d_out;

    cudaFuncSetAttribute(gemm_kernel, cudaFuncAttributeMaxDynamicSharedMemorySize, SMEM_TOTAL);

    init_kernel<<<(K_CODES + 255) / 256, 256>>>();
    norm_split_kernel<<<(N_ROWS + K_CODES) / 8, 256>>>(z, emb);
    gemm_kernel<<<dim3(N_ROWS / 128, K_CODES / 128), 256, SMEM_TOTAL>>>();
    combine_kernel<<<N_ROWS / 256, 256>>>();
    fixup_kernel<<<64, 256>>>();
    passB_kernel<<<K_CODES / 128, 256>>>();
    zq_kernel<<<N_ROWS / 8, 256>>>(out);
    finalize_kernel<<<1, 256>>>(out);
}